// round 7
// baseline (speedup 1.0000x reference)
#include <cuda_runtime.h>
#include <cuda_fp16.h>
#include <math.h>
#include <stdint.h>

#define BB 2048
#define SS 200
#define DD 128
#define HH 64
#define MASK_SCALE 1e10f
#define NT 256
#define NW (NT / 32)
#define ROWS_PER_WARP (SS / NW)      // 25
#define NSTRIP 13                    // ceil(200/16); strip 12 rows 200..207 discarded

#define ASTRIDE 272                  // bytes per A row (136 fp16) = 17*16
#define BSTRIDE 144                  // bytes per B row (72 fp16)  = 9*16

// ---- smem byte layout ----
#define A_OFF      0                         // 200*272 = 54400
#define B_OFF      54400                     // 128*144 = 18432 (dead after GEMM)
#define SM_SCRATCH B_OFF                     // pool scratch aliases B: 8*128 f = 4096
#define SM_RED     (B_OFF + 4096)            // 8 f (aliases B)
#define SM_RED2    (B_OFF + 4128)            // 8 f (aliases B)
#define SM_ALPHA   72832                     // 256 f
#define SM_CO      73856                     // 64 float2 = 512
#define SMEM_BYTES 74368                     // 72.6 KB -> 3 CTAs/SM

typedef unsigned long long u64;

// Precomputed globals
__device__ __half g_Bh[DD * 72];   // (W1+W2) fp16, [k][c] padded to 72
__device__ float g_Wb[DD * HH];    // W3 - W2
__device__ float g_c[BB * HH];     // tgt @ Wb + W_bias

__device__ __forceinline__ uint32_t smem_u32(const void* p) {
    return (uint32_t)__cvta_generic_to_shared(p);
}
__device__ __forceinline__ void cpa16(void* s, const void* g) {
    asm volatile("cp.async.cg.shared.global [%0], [%1], 16;" :: "r"(smem_u32(s)), "l"(g));
}
#define CP_COMMIT() asm volatile("cp.async.commit_group;")
#define CP_WAIT0()  asm volatile("cp.async.wait_group 0;")

__device__ __forceinline__ void ldsm4(uint32_t* r, uint32_t addr) {
    asm volatile("ldmatrix.sync.aligned.m8n8.x4.shared.b16 {%0,%1,%2,%3}, [%4];"
                 : "=r"(r[0]), "=r"(r[1]), "=r"(r[2]), "=r"(r[3]) : "r"(addr));
}
__device__ __forceinline__ void ldsm4t(uint32_t* r, uint32_t addr) {
    asm volatile("ldmatrix.sync.aligned.m8n8.x4.trans.shared.b16 {%0,%1,%2,%3}, [%4];"
                 : "=r"(r[0]), "=r"(r[1]), "=r"(r[2]), "=r"(r[3]) : "r"(addr));
}
__device__ __forceinline__ void mma16816(float* c, const uint32_t* a,
                                         uint32_t b0, uint32_t b1) {
    asm volatile(
        "mma.sync.aligned.m16n8k16.row.col.f32.f16.f16.f32 "
        "{%0,%1,%2,%3}, {%4,%5,%6,%7}, {%8,%9}, {%0,%1,%2,%3};"
        : "+f"(c[0]), "+f"(c[1]), "+f"(c[2]), "+f"(c[3])
        : "r"(a[0]), "r"(a[1]), "r"(a[2]), "r"(a[3]), "r"(b0), "r"(b1));
}

__global__ void fold_w_kernel(const float* __restrict__ W) {
    int idx = blockIdx.x * blockDim.x + threadIdx.x;   // DD*HH
    if (idx < DD * HH) {
        int k = idx >> 6, c = idx & 63;
        float w1 = W[k * HH + c];
        float w2 = W[(DD + k) * HH + c];
        float w3 = W[(2 * DD + k) * HH + c];
        g_Wb[k * HH + c] = w3 - w2;
        g_Bh[k * 72 + c] = __float2half_rn(w1 + w2);
    }
}

__global__ void cvec_kernel(const float* __restrict__ target,
                            const float* __restrict__ W_bias) {
    __shared__ float tgt[DD];
    int b = blockIdx.x;
    for (int i = threadIdx.x; i < DD; i += blockDim.x)
        tgt[i] = target[(size_t)b * DD + i];
    __syncthreads();
    int h = threadIdx.x;
    if (h < HH) {
        float acc = 0.f;
#pragma unroll 8
        for (int d = 0; d < DD; d++)
            acc = fmaf(tgt[d], g_Wb[d * HH + h], acc);
        g_c[b * HH + h] = acc + W_bias[h];
    }
}

__global__ __launch_bounds__(NT, 3)
void ta_main_kernel(const float* __restrict__ his,
                    const float* __restrict__ mask,
                    const float* __restrict__ O,
                    const float* __restrict__ O_bias,
                    float* __restrict__ out) {
    extern __shared__ __align__(16) char sm[];
    float*  alpha = (float*)(sm + SM_ALPHA);
    float2* cO_s  = (float2*)(sm + SM_CO);
    float*  scr   = (float*)(sm + SM_SCRATCH);
    float*  red   = (float*)(sm + SM_RED);
    float*  red2  = (float*)(sm + SM_RED2);

    const int b = blockIdx.x;
    const int tid = threadIdx.x;
    const int wid = tid >> 5;
    const int lane = tid & 31;
    const uint32_t smem_base = smem_u32(sm);

    // ---- Phase 0: loads ----
    for (int i = tid; i < 18432 / 16; i += NT)
        cpa16(sm + B_OFF + i * 16, (const char*)g_Bh + i * 16);
    CP_COMMIT();

    const float ob = O_bias[0];
    // alpha pre-bias: ob - mask*MASK_SCALE (GEMM adds its v on top, same thread)
    if (tid < SS) alpha[tid] = ob - mask[(size_t)b * SS + tid] * MASK_SCALE;
    if (tid < HH) cO_s[tid] = make_float2(g_c[b * HH + tid], O[tid]);

    // his load + fp32->fp16 + STS (row-major, ASTRIDE)
    {
        const int k0 = 4 * lane;
        const float* hb = his + ((size_t)b * SS + (size_t)wid * ROWS_PER_WARP) * DD + k0;
#pragma unroll 5
        for (int i = 0; i < ROWS_PER_WARP; i++) {
            int s = wid * ROWS_PER_WARP + i;
            float4 v = *(const float4*)(hb + (size_t)i * DD);
            __half2 p01 = __floats2half2_rn(v.x, v.y);
            __half2 p23 = __floats2half2_rn(v.z, v.w);
            u64 hp = ((u64)*(uint32_t*)&p23 << 32) | *(uint32_t*)&p01;
            *(u64*)(sm + A_OFF + s * ASTRIDE + k0 * 2) = hp;
        }
    }

    CP_WAIT0();
    __syncthreads();

    // ---- Phase 1: GEMM via mma.sync fp16, 2 sequential strips/warp ----
    {
        const int g = lane >> 3;
        const int r = lane & 7;
        const int arow_l = r + (g & 1) * 8;
        const int acol_l = (g >> 1) * 16;
        const int brow_l = r + (g & 1) * 8;
        const uint32_t aB = smem_base + A_OFF;
        const uint32_t bH = smem_base + B_OFF + brow_l * BSTRIDE + (g >> 1) * 16;
        const int cbase = 2 * (lane & 3);

#pragma unroll 1
        for (int rnd = 0; rnd < 2; rnd++) {
            const int strip = wid + rnd * 8;
            if (strip >= NSTRIP) break;

            float c[8][4];
#pragma unroll
            for (int nt = 0; nt < 8; nt++)
#pragma unroll
                for (int q = 0; q < 4; q++) c[nt][q] = 0.f;

            const uint32_t Ab = aB + (strip * 16 + arow_l) * ASTRIDE + acol_l;
#pragma unroll
            for (int kk = 0; kk < 8; kk++) {
                uint32_t a[4];
                ldsm4(a, Ab + kk * 32);   // strip 12 rows 200..207 read into B region: discarded
                const uint32_t koff = kk * 16 * BSTRIDE;
#pragma unroll
                for (int np2 = 0; np2 < 4; np2++) {
                    uint32_t bf[4];
                    ldsm4t(bf, bH + koff + np2 * 32);
                    mma16816(c[2 * np2],     a, bf[0], bf[1]);
                    mma16816(c[2 * np2 + 1], a, bf[2], bf[3]);
                }
            }

            float v0 = 0.f, v1 = 0.f;
#pragma unroll
            for (int nt = 0; nt < 8; nt++) {
                int col0 = nt * 8 + cbase;
                float2 co0 = cO_s[col0];
                float2 co1 = cO_s[col0 + 1];
                v0 = fmaf(fmaxf(c[nt][0] + co0.x, 0.f), co0.y, v0);
                v0 = fmaf(fmaxf(c[nt][1] + co1.x, 0.f), co1.y, v0);
                v1 = fmaf(fmaxf(c[nt][2] + co0.x, 0.f), co0.y, v1);
                v1 = fmaf(fmaxf(c[nt][3] + co1.x, 0.f), co1.y, v1);
            }
            v0 += __shfl_xor_sync(0xffffffffu, v0, 1);
            v0 += __shfl_xor_sync(0xffffffffu, v0, 2);
            v1 += __shfl_xor_sync(0xffffffffu, v1, 1);
            v1 += __shfl_xor_sync(0xffffffffu, v1, 2);
            if ((lane & 3) == 0) {
                int s0 = strip * 16 + (lane >> 2);
                if (s0 < SS)     alpha[s0]     = v0 + alpha[s0];
                if (s0 + 8 < SS) alpha[s0 + 8] = v1 + alpha[s0 + 8];
            }
        }
    }
    __syncthreads();

    // ---- Phase 2: softmax over alpha[0..SS) ----
    {
        float vv = (tid < SS) ? alpha[tid] : -INFINITY;
        float m = vv;
#pragma unroll
        for (int off = 16; off > 0; off >>= 1)
            m = fmaxf(m, __shfl_xor_sync(0xffffffffu, m, off));
        if (lane == 0) red[wid] = m;
        __syncthreads();
        m = red[0];
#pragma unroll
        for (int w = 1; w < NW; w++) m = fmaxf(m, red[w]);

        float e = (tid < SS) ? __expf(vv - m) : 0.f;
        float ssum = e;
#pragma unroll
        for (int off = 16; off > 0; off >>= 1)
            ssum += __shfl_xor_sync(0xffffffffu, ssum, off);
        if (lane == 0) red2[wid] = ssum;
        __syncthreads();
        float tot = 0.f;
#pragma unroll
        for (int w = 0; w < NW; w++) tot += red2[w];

        if (tid < SS) alpha[tid] = e / tot;
    }
    __syncthreads();

    // ---- Phase 3: pooling out[b,d] = sum_s attn[s] * A[s,d]  (LDS.64) ----
    {
        const int p = tid & 31;          // d-quad: d = 4p..4p+3
        const int q = wid;               // s-group of 25 rows
        float a0 = 0.f, a1 = 0.f, a2 = 0.f, a3 = 0.f;
        const int sbeg = q * ROWS_PER_WARP;
#pragma unroll 5
        for (int i = 0; i < ROWS_PER_WARP; i++) {
            int s = sbeg + i;
            uint2 hv = *(uint2*)(sm + A_OFF + s * ASTRIDE + p * 8);
            float2 f01 = __half22float2(*(__half2*)&hv.x);
            float2 f23 = __half22float2(*(__half2*)&hv.y);
            float a = alpha[s];
            a0 = fmaf(a, f01.x, a0);
            a1 = fmaf(a, f01.y, a1);
            a2 = fmaf(a, f23.x, a2);
            a3 = fmaf(a, f23.y, a3);
        }
        *(float4*)(scr + q * 128 + p * 4) = make_float4(a0, a1, a2, a3);
        __syncthreads();
        if (tid < DD) {
            float r2 = 0.f;
#pragma unroll
            for (int g2 = 0; g2 < NW; g2++) r2 += scr[g2 * 128 + tid];
            out[(size_t)b * DD + tid] = r2;
        }
    }
}

extern "C" void kernel_launch(void* const* d_in, const int* in_sizes, int n_in,
                              void* d_out, int out_size) {
    const float* his    = (const float*)d_in[0];
    const float* target = (const float*)d_in[1];
    const float* mask   = (const float*)d_in[2];
    const float* W      = (const float*)d_in[3];
    const float* W_bias = (const float*)d_in[4];
    const float* O      = (const float*)d_in[5];
    const float* O_bias = (const float*)d_in[6];
    float* out = (float*)d_out;

    cudaFuncSetAttribute(ta_main_kernel,
                         cudaFuncAttributeMaxDynamicSharedMemorySize, SMEM_BYTES);

    fold_w_kernel<<<(DD * HH + 255) / 256, 256>>>(W);
    cvec_kernel<<<BB, 128>>>(target, W_bias);
    ta_main_kernel<<<BB, NT, SMEM_BYTES>>>(his, mask, O, O_bias, out);
}

// round 8
// speedup vs baseline: 1.0343x; 1.0343x over previous
#include <cuda_runtime.h>
#include <cuda_fp16.h>
#include <math.h>
#include <stdint.h>

#define BB 2048
#define SS 200
#define DD 128
#define HH 64
#define MASK_SCALE 1e10f
#define NT 256
#define NW (NT / 32)
#define ROWS_PER_WARP (SS / NW)      // 25 (pooling granularity)
#define NSTRIP 13                    // ceil(200/16); strip 12 rows 200..207 unused

#define ASTRIDE 272                  // bytes per A row (136 fp16) = 17*16
#define BSTRIDE 144                  // bytes per B row (72 fp16)  = 9*16

// ---- smem byte layout ----
#define A_OFF      0                         // 200*272 = 54400
#define B_OFF      54400                     // 128*144 = 18432 (dead after GEMM)
#define SM_SCRATCH B_OFF                     // pool scratch aliases B: 8*128 f
#define SM_RED     (B_OFF + 4096)            // 8 f (aliases B)
#define SM_RED2    (B_OFF + 4128)            // 8 f (aliases B)
#define SM_ALPHA   72832                     // 256 f
#define SM_CO      73856                     // 64 float2 = 512
#define SMEM_BYTES 74368                     // 72.6 KB -> 2 CTAs/SM

typedef unsigned long long u64;

// Precomputed globals
__device__ __half g_Bh[DD * 72];   // (W1+W2) fp16, [k][c] padded to 72
__device__ float g_Wb[DD * HH];    // W3 - W2
__device__ float g_c[BB * HH];     // tgt @ Wb + W_bias

__device__ __forceinline__ uint32_t smem_u32(const void* p) {
    return (uint32_t)__cvta_generic_to_shared(p);
}
__device__ __forceinline__ void cpa16(void* s, const void* g) {
    asm volatile("cp.async.cg.shared.global [%0], [%1], 16;" :: "r"(smem_u32(s)), "l"(g));
}
#define CP_COMMIT() asm volatile("cp.async.commit_group;")
#define CP_WAIT0()  asm volatile("cp.async.wait_group 0;")

__device__ __forceinline__ void ldsm4(uint32_t* r, uint32_t addr) {
    asm volatile("ldmatrix.sync.aligned.m8n8.x4.shared.b16 {%0,%1,%2,%3}, [%4];"
                 : "=r"(r[0]), "=r"(r[1]), "=r"(r[2]), "=r"(r[3]) : "r"(addr));
}
__device__ __forceinline__ void ldsm4t(uint32_t* r, uint32_t addr) {
    asm volatile("ldmatrix.sync.aligned.m8n8.x4.trans.shared.b16 {%0,%1,%2,%3}, [%4];"
                 : "=r"(r[0]), "=r"(r[1]), "=r"(r[2]), "=r"(r[3]) : "r"(addr));
}
__device__ __forceinline__ void mma16816(float* c, const uint32_t* a,
                                         uint32_t b0, uint32_t b1) {
    asm volatile(
        "mma.sync.aligned.m16n8k16.row.col.f32.f16.f16.f32 "
        "{%0,%1,%2,%3}, {%4,%5,%6,%7}, {%8,%9}, {%0,%1,%2,%3};"
        : "+f"(c[0]), "+f"(c[1]), "+f"(c[2]), "+f"(c[3])
        : "r"(a[0]), "r"(a[1]), "r"(a[2]), "r"(a[3]), "r"(b0), "r"(b1));
}

__global__ void fold_w_kernel(const float* __restrict__ W) {
    int idx = blockIdx.x * blockDim.x + threadIdx.x;   // DD*HH
    if (idx < DD * HH) {
        int k = idx >> 6, c = idx & 63;
        float w1 = W[k * HH + c];
        float w2 = W[(DD + k) * HH + c];
        float w3 = W[(2 * DD + k) * HH + c];
        g_Wb[k * HH + c] = w3 - w2;
        g_Bh[k * 72 + c] = __float2half_rn(w1 + w2);
    }
}

__global__ void cvec_kernel(const float* __restrict__ target,
                            const float* __restrict__ W_bias) {
    __shared__ float tgt[DD];
    int b = blockIdx.x;
    for (int i = threadIdx.x; i < DD; i += blockDim.x)
        tgt[i] = target[(size_t)b * DD + i];
    __syncthreads();
    int h = threadIdx.x;
    if (h < HH) {
        float acc = 0.f;
#pragma unroll 8
        for (int d = 0; d < DD; d++)
            acc = fmaf(tgt[d], g_Wb[d * HH + h], acc);
        g_c[b * HH + h] = acc + W_bias[h];
    }
}

__global__ __launch_bounds__(NT, 2)
void ta_main_kernel(const float* __restrict__ his,
                    const float* __restrict__ mask,
                    const float* __restrict__ O,
                    const float* __restrict__ O_bias,
                    float* __restrict__ out) {
    extern __shared__ __align__(16) char sm[];
    float*  alpha = (float*)(sm + SM_ALPHA);
    float2* cO_s  = (float2*)(sm + SM_CO);
    float*  scr   = (float*)(sm + SM_SCRATCH);
    float*  red   = (float*)(sm + SM_RED);
    float*  red2  = (float*)(sm + SM_RED2);

    const int b = blockIdx.x;
    const int tid = threadIdx.x;
    const int wid = tid >> 5;
    const int lane = tid & 31;
    const uint32_t smem_base = smem_u32(sm);

    // ---- Phase 0a: B weights via cp.async; alpha pre-bias; cO ----
    for (int i = tid; i < 18432 / 16; i += NT)
        cpa16(sm + B_OFF + i * 16, (const char*)g_Bh + i * 16);
    CP_COMMIT();

    const float ob = O_bias[0];
    if (tid < SS) alpha[tid] = ob - mask[(size_t)b * SS + tid] * MASK_SCALE;
    if (tid < HH) cO_s[tid] = make_float2(g_c[b * HH + tid], O[tid]);

    CP_WAIT0();
    __syncthreads();     // B + alpha pre-bias + cO visible block-wide

    // ---- Phase 0b: OWN-STRIP loading (warp-local), batched 8-deep LDG ----
    {
        const int k0 = 4 * lane;
#pragma unroll 1
        for (int rnd = 0; rnd < 2; rnd++) {
            const int strip = wid + rnd * 8;
            if (strip >= NSTRIP) break;
            const int base = strip * 16;
            const int nrows = (base + 16 <= SS) ? 16 : (SS - base);   // 16 or 8
            const float* hb = his + ((size_t)b * SS + base) * DD + k0;
#pragma unroll 1
            for (int g0 = 0; g0 < nrows; g0 += 8) {
                float4 v[8];
#pragma unroll
                for (int j = 0; j < 8; j++)
                    if (g0 + j < nrows) v[j] = *(const float4*)(hb + (size_t)(g0 + j) * DD);
#pragma unroll
                for (int j = 0; j < 8; j++)
                    if (g0 + j < nrows) {
                        int s = base + g0 + j;
                        __half2 p01 = __floats2half2_rn(v[j].x, v[j].y);
                        __half2 p23 = __floats2half2_rn(v[j].z, v[j].w);
                        u64 hp = ((u64)*(uint32_t*)&p23 << 32) | *(uint32_t*)&p01;
                        *(u64*)(sm + A_OFF + s * ASTRIDE + k0 * 2) = hp;
                    }
            }
        }
    }
    __syncwarp();        // warp's own rows visible to itself -> GEMM can start NOW

    // ---- Phase 1: GEMM (dual strip, B-frag reuse) on own rows ----
    {
        const int g = lane >> 3;
        const int r = lane & 7;
        const int arow_l = r + (g & 1) * 8;
        const int acol_l = (g >> 1) * 16;
        const int brow_l = r + (g & 1) * 8;
        const uint32_t aB = smem_base + A_OFF;
        const uint32_t bH = smem_base + B_OFF + brow_l * BSTRIDE + (g >> 1) * 16;

        const int strip0 = wid;
        const int strip1 = wid + 8;
        const bool two = (strip1 < NSTRIP);

        float c0[8][4], c1[8][4];
#pragma unroll
        for (int nt = 0; nt < 8; nt++)
#pragma unroll
            for (int q = 0; q < 4; q++) { c0[nt][q] = 0.f; c1[nt][q] = 0.f; }

        const uint32_t Ab0 = aB + (strip0 * 16 + arow_l) * ASTRIDE + acol_l;
        const uint32_t Ab1 = aB + (strip1 * 16 + arow_l) * ASTRIDE + acol_l;

#pragma unroll
        for (int kk = 0; kk < 8; kk++) {
            uint32_t a0[4], a1[4];
            ldsm4(a0, Ab0 + kk * 32);
            if (two) ldsm4(a1, Ab1 + kk * 32);   // strip 12 rows 200..207: garbage, discarded
            const uint32_t koff = kk * 16 * BSTRIDE;
#pragma unroll
            for (int np2 = 0; np2 < 4; np2++) {
                uint32_t bf[4];
                ldsm4t(bf, bH + koff + np2 * 32);
                mma16816(c0[2 * np2],     a0, bf[0], bf[1]);
                mma16816(c0[2 * np2 + 1], a0, bf[2], bf[3]);
                if (two) {
                    mma16816(c1[2 * np2],     a1, bf[0], bf[1]);
                    mma16816(c1[2 * np2 + 1], a1, bf[2], bf[3]);
                }
            }
        }

        const int cbase = 2 * (lane & 3);
#pragma unroll
        for (int pass = 0; pass < 2; pass++) {
            if (pass == 1 && !two) break;
            float (*c)[4] = pass ? c1 : c0;
            const int strip = pass ? strip1 : strip0;
            float v0 = 0.f, v1 = 0.f;
#pragma unroll
            for (int nt = 0; nt < 8; nt++) {
                int col0 = nt * 8 + cbase;
                float2 co0 = cO_s[col0];
                float2 co1 = cO_s[col0 + 1];
                v0 = fmaf(fmaxf(c[nt][0] + co0.x, 0.f), co0.y, v0);
                v0 = fmaf(fmaxf(c[nt][1] + co1.x, 0.f), co1.y, v0);
                v1 = fmaf(fmaxf(c[nt][2] + co0.x, 0.f), co0.y, v1);
                v1 = fmaf(fmaxf(c[nt][3] + co1.x, 0.f), co1.y, v1);
            }
            v0 += __shfl_xor_sync(0xffffffffu, v0, 1);
            v0 += __shfl_xor_sync(0xffffffffu, v0, 2);
            v1 += __shfl_xor_sync(0xffffffffu, v1, 1);
            v1 += __shfl_xor_sync(0xffffffffu, v1, 2);
            if ((lane & 3) == 0) {
                int s0 = strip * 16 + (lane >> 2);
                if (s0 < SS)     alpha[s0]     = v0 + alpha[s0];
                if (s0 + 8 < SS) alpha[s0 + 8] = v1 + alpha[s0 + 8];
            }
        }
    }
    __syncthreads();

    // ---- Phase 2: softmax over alpha[0..SS) ----
    {
        float vv = (tid < SS) ? alpha[tid] : -INFINITY;
        float m = vv;
#pragma unroll
        for (int off = 16; off > 0; off >>= 1)
            m = fmaxf(m, __shfl_xor_sync(0xffffffffu, m, off));
        if (lane == 0) red[wid] = m;
        __syncthreads();
        m = red[0];
#pragma unroll
        for (int w = 1; w < NW; w++) m = fmaxf(m, red[w]);

        float e = (tid < SS) ? __expf(vv - m) : 0.f;
        float ssum = e;
#pragma unroll
        for (int off = 16; off > 0; off >>= 1)
            ssum += __shfl_xor_sync(0xffffffffu, ssum, off);
        if (lane == 0) red2[wid] = ssum;
        __syncthreads();
        float tot = 0.f;
#pragma unroll
        for (int w = 0; w < NW; w++) tot += red2[w];

        if (tid < SS) alpha[tid] = e / tot;
    }
    __syncthreads();

    // ---- Phase 3: pooling out[b,d] = sum_s attn[s] * A[s,d]  (LDS.64) ----
    {
        const int p = tid & 31;          // d-quad: d = 4p..4p+3
        const int q = wid;               // s-group of 25 rows
        float a0 = 0.f, a1 = 0.f, a2 = 0.f, a3 = 0.f;
        const int sbeg = q * ROWS_PER_WARP;
#pragma unroll 5
        for (int i = 0; i < ROWS_PER_WARP; i++) {
            int s = sbeg + i;
            uint2 hv = *(uint2*)(sm + A_OFF + s * ASTRIDE + p * 8);
            float2 f01 = __half22float2(*(__half2*)&hv.x);
            float2 f23 = __half22float2(*(__half2*)&hv.y);
            float a = alpha[s];
            a0 = fmaf(a, f01.x, a0);
            a1 = fmaf(a, f01.y, a1);
            a2 = fmaf(a, f23.x, a2);
            a3 = fmaf(a, f23.y, a3);
        }
        *(float4*)(scr + q * 128 + p * 4) = make_float4(a0, a1, a2, a3);
        __syncthreads();
        if (tid < DD) {
            float r2 = 0.f;
#pragma unroll
            for (int g2 = 0; g2 < NW; g2++) r2 += scr[g2 * 128 + tid];
            out[(size_t)b * DD + tid] = r2;
        }
    }
}

extern "C" void kernel_launch(void* const* d_in, const int* in_sizes, int n_in,
                              void* d_out, int out_size) {
    const float* his    = (const float*)d_in[0];
    const float* target = (const float*)d_in[1];
    const float* mask   = (const float*)d_in[2];
    const float* W      = (const float*)d_in[3];
    const float* W_bias = (const float*)d_in[4];
    const float* O      = (const float*)d_in[5];
    const float* O_bias = (const float*)d_in[6];
    float* out = (float*)d_out;

    cudaFuncSetAttribute(ta_main_kernel,
                         cudaFuncAttributeMaxDynamicSharedMemorySize, SMEM_BYTES);

    fold_w_kernel<<<(DD * HH + 255) / 256, 256>>>(W);
    cvec_kernel<<<BB, 128>>>(target, W_bias);
    ta_main_kernel<<<BB, NT, SMEM_BYTES>>>(his, mask, O, O_bias, out);
}